// round 10
// baseline (speedup 1.0000x reference)
#include <cuda_runtime.h>

#define FULLMASK 0xffffffffu

// Problem dims (fixed by the dataset)
#define Bb 16
#define Ss 256
#define Nn 16
#define Dd 6
#define Hh 16
#define CHAINS 256
#define NSEG 16
#define SEGL 16

// Per-row projection partials: [row][hq][d] = 65536 x 24 floats = 6.3 MB
__device__ float g_part[(size_t)CHAINS * Ss * 24];

// ---- Clifford sign machinery (5-bit blade masks, matches reference) ----
__host__ __device__ constexpr unsigned popc5(unsigned v) {
    v &= 31u;
    return (v & 1u) + ((v >> 1) & 1u) + ((v >> 2) & 1u) + ((v >> 3) & 1u) + ((v >> 4) & 1u);
}
__host__ __device__ constexpr int csn(unsigned a, unsigned b) {
    a >>= 1; int s = 0;
    while (a) { s += (int)popc5(a & b); a >>= 1; }
    return s & 1;
}
__host__ __device__ constexpr unsigned lift4(unsigned L) {
    L &= 15u;
    unsigned p = (L ^ (L >> 1) ^ (L >> 2) ^ (L >> 3)) & 1u;
    return L | (p << 4);
}
__host__ __device__ constexpr unsigned long long buildCT() {
    unsigned long long t = 0;
    for (unsigned m = 0; m < 4; ++m)
        for (unsigned s = 0; s < 4; ++s)
            for (unsigned jr = 0; jr < 4; ++jr)
                if (csn(lift4((m << 2) | s), lift4(jr)))
                    t |= 1ull << (m * 16 + s * 4 + jr);
    return t;
}
static constexpr unsigned long long CT_TABLE = buildCT();
#define CT(m, s, jr) (int)((CT_TABLE >> ((m) * 16 + (s) * 4 + (jr))) & 1ull)

// One mask-m term of out = A*B (16-dim split-ideal XOR-conv).
#define GP_MASK(M, dv, SMC, pm0, pm1, pm2, pm3, q0, q1, q2, q3) do {            \
    const float as0 = __uint_as_float(__float_as_uint((dv).x) ^ (SMC)[0]);      \
    const float as1 = __uint_as_float(__float_as_uint((dv).y) ^ (SMC)[1]);      \
    const float as2 = __uint_as_float(__float_as_uint((dv).z) ^ (SMC)[2]);      \
    const float as3 = __uint_as_float(__float_as_uint((dv).w) ^ (SMC)[3]);      \
    q0 = fmaf(CT(M,0,0) ? -as0 : as0, pm0, q0);                                 \
    q1 = fmaf(CT(M,0,1) ? -as0 : as0, pm1, q1);                                 \
    q2 = fmaf(CT(M,0,2) ? -as0 : as0, pm2, q2);                                 \
    q3 = fmaf(CT(M,0,3) ? -as0 : as0, pm3, q3);                                 \
    q0 = fmaf(CT(M,1,1) ? -as1 : as1, pm1, q0);                                 \
    q1 = fmaf(CT(M,1,0) ? -as1 : as1, pm0, q1);                                 \
    q2 = fmaf(CT(M,1,3) ? -as1 : as1, pm3, q2);                                 \
    q3 = fmaf(CT(M,1,2) ? -as1 : as1, pm2, q3);                                 \
    q0 = fmaf(CT(M,2,2) ? -as2 : as2, pm2, q0);                                 \
    q1 = fmaf(CT(M,2,3) ? -as2 : as2, pm3, q1);                                 \
    q2 = fmaf(CT(M,2,0) ? -as2 : as2, pm0, q2);                                 \
    q3 = fmaf(CT(M,2,1) ? -as2 : as2, pm1, q3);                                 \
    q0 = fmaf(CT(M,3,3) ? -as3 : as3, pm3, q0);                                 \
    q1 = fmaf(CT(M,3,2) ? -as3 : as3, pm2, q1);                                 \
    q2 = fmaf(CT(M,3,1) ? -as3 : as3, pm1, q2);                                 \
    q3 = fmaf(CT(M,3,0) ? -as3 : as3, pm0, q3);                                 \
} while (0)

__device__ __forceinline__ void build_smC(int g2, unsigned smC[4][4]) {
#pragma unroll
    for (int m = 0; m < 4; ++m) {
        const unsigned jhi = lift4((unsigned)(((g2 ^ m) & 3) << 2));
#pragma unroll
        for (int s = 0; s < 4; ++s)
            smC[m][s] = (unsigned)csn(lift4((unsigned)((m << 2) | s)), jhi) << 31;
    }
}

// SMEM layout (float4 units): sP[256][32] | sD[16][2][32] | sC[16][32]
#define SP_ENT (256 * 32)
#define SD_ENT (16 * 2 * 32)
#define SC_ENT (16 * 32)
#define SMEM_BYTES ((SP_ENT + SD_ENT + SC_ENT) * 16)

// ---------------------------------------------------------------------------
// Fused scan kernel. Block = (chain, headquad): 512 threads (16 warps), one
// warp per segment. P never leaves SMEM.
// ---------------------------------------------------------------------------
__global__ void __launch_bounds__(512) fused_kernel(
    const float* __restrict__ x,      // [B,S,N,D]
    const float* __restrict__ W_in,   // [D, H*32]
    const float* __restrict__ b_in,   // [H*32]
    const float* __restrict__ W_out)  // [H*32, D]
{
    extern __shared__ float4 smem[];
    float4* sP = smem;                 // [step][lane], step = seg*16+i
    float4* sD = smem + SP_ENT;        // [warp][buf][lane]
    float4* sC = smem + SP_ENT + SD_ENT; // [seg][lane]

    const int wid  = threadIdx.x >> 5;     // segment 0..15
    const int lane = threadIdx.x & 31;
    const int c  = blockIdx.x >> 2;
    const int hq = blockIdx.x & 3;
    const int hw   = lane >> 3;
    const int half = (lane >> 2) & 1;
    const int g2   = lane & 3;
    const int h  = hq * 4 + hw;
    const int b  = c >> 4;
    const int n  = c & (Nn - 1);
    const int dlbase = lane & 28;
    const int seg = wid;

    unsigned smC[4][4];
    build_smC(g2, smC);

    // ---- transformed input weights (per lane) ----
    float wi[4][Dd], bi[4];
#pragma unroll
    for (int r = 0; r < 4; ++r) {
        const unsigned E  = lift4((unsigned)(g2 * 4 + r));
        const unsigned Ed = E ^ 31u;
        const float sIn  = csn(31u, Ed) ? -1.0f : 1.0f;
        const float coef = half ? -sIn : sIn;
        const int colE = h * 32 + (int)E, colD = h * 32 + (int)Ed;
#pragma unroll
        for (int d = 0; d < Dd; ++d)
            wi[r][d] = __ldg(W_in + d * 512 + colE) + coef * __ldg(W_in + d * 512 + colD);
        bi[r] = __ldg(b_in + colE) + coef * __ldg(b_in + colD);
    }

    // =========================== Phase A ===================================
    // local prefixes P_{seg,i} = dl_i * ... * dl_0, stored to sP rows
    {
        float w0 = 0.f, w1 = 0.f, w2 = 0.f, w3 = 0.f;
        const float* xp = x + (((size_t)b * Ss + seg * SEGL) * Nn + n) * Dd;

#pragma unroll 1
        for (int i = 0; i < SEGL; ++i) {
            float cx[Dd];
#pragma unroll
            for (int d = 0; d < Dd; ++d) cx[d] = __ldg(xp + d);
            xp += Nn * Dd;

            // dl = transformed (x@W_in + b_in ; +1 at label 0)
            float dl0 = bi[0], dl1 = bi[1], dl2 = bi[2], dl3 = bi[3];
#pragma unroll
            for (int d = 0; d < Dd; ++d) {
                dl0 = fmaf(wi[0][d], cx[d], dl0);
                dl1 = fmaf(wi[1][d], cx[d], dl1);
                dl2 = fmaf(wi[2][d], cx[d], dl2);
                dl3 = fmaf(wi[3][d], cx[d], dl3);
            }
            if (g2 == 0) dl0 += 1.0f;

            if (i == 0) {
                // GP(dl, identity) = dl
                w0 = dl0; w1 = dl1; w2 = dl2; w3 = dl3;
            } else {
                const int buf = i & 1;
                sD[(wid * 2 + buf) * 32 + lane] = make_float4(dl0, dl1, dl2, dl3);
                __syncwarp();

                const int prow = seg * SEGL + i - 1;
                float pA0 = 0.f, pA1 = 0.f, pA2 = 0.f, pA3 = 0.f;
                float pB0 = 0.f, pB1 = 0.f, pB2 = 0.f, pB3 = 0.f;
                {   const float4 dv = sD[(wid * 2 + buf) * 32 + dlbase];
                    GP_MASK(0, dv, smC[0], w0, w1, w2, w3, pA0, pA1, pA2, pA3);
                }
                {   const float4 wv = sP[prow * 32 + (lane ^ 1)];
                    const float4 dv = sD[(wid * 2 + buf) * 32 + (dlbase | 1)];
                    GP_MASK(1, dv, smC[1], wv.x, wv.y, wv.z, wv.w, pB0, pB1, pB2, pB3);
                }
                {   const float4 wv = sP[prow * 32 + (lane ^ 2)];
                    const float4 dv = sD[(wid * 2 + buf) * 32 + (dlbase | 2)];
                    GP_MASK(2, dv, smC[2], wv.x, wv.y, wv.z, wv.w, pA0, pA1, pA2, pA3);
                }
                {   const float4 wv = sP[prow * 32 + (lane ^ 3)];
                    const float4 dv = sD[(wid * 2 + buf) * 32 + (dlbase | 3)];
                    GP_MASK(3, dv, smC[3], wv.x, wv.y, wv.z, wv.w, pB0, pB1, pB2, pB3);
                }
                w0 = pA0 + pB0; w1 = pA1 + pB1; w2 = pA2 + pB2; w3 = pA3 + pB3;
            }
            sP[(seg * SEGL + i) * 32 + lane] = make_float4(w0, w1, w2, w3);
        }
    }
    __syncthreads();

    // =========================== Phase B ===================================
    // warp 0: C_{s+1} = normalize(T_s * C_s), T_s = sP[s*16+15]
    if (wid == 0) {
        float c0 = (g2 == 0) ? 1.0f : 0.0f, c1 = 0.f, c2 = 0.f, c3 = 0.f;
#pragma unroll 1
        for (int s = 0; s < NSEG; ++s) {
            const int buf = s & 1;
            sC[s * 32 + lane] = make_float4(c0, c1, c2, c3);

            const float4 T = sP[(s * SEGL + SEGL - 1) * 32 + lane];
            sD[(0 * 2 + buf) * 32 + lane] = T;                       // dv side
            sD[(1 * 2 + buf) * 32 + lane] = make_float4(c0, c1, c2, c3); // wv side
            __syncwarp();

            float pA0 = 0.f, pA1 = 0.f, pA2 = 0.f, pA3 = 0.f;
            float pB0 = 0.f, pB1 = 0.f, pB2 = 0.f, pB3 = 0.f;
            {   const float4 dv = sD[(0 * 2 + buf) * 32 + dlbase];
                GP_MASK(0, dv, smC[0], c0, c1, c2, c3, pA0, pA1, pA2, pA3);
            }
            {   const float4 wv = sD[(1 * 2 + buf) * 32 + (lane ^ 1)];
                const float4 dv = sD[(0 * 2 + buf) * 32 + (dlbase | 1)];
                GP_MASK(1, dv, smC[1], wv.x, wv.y, wv.z, wv.w, pB0, pB1, pB2, pB3);
            }
            {   const float4 wv = sD[(1 * 2 + buf) * 32 + (lane ^ 2)];
                const float4 dv = sD[(0 * 2 + buf) * 32 + (dlbase | 2)];
                GP_MASK(2, dv, smC[2], wv.x, wv.y, wv.z, wv.w, pA0, pA1, pA2, pA3);
            }
            {   const float4 wv = sD[(1 * 2 + buf) * 32 + (lane ^ 3)];
                const float4 dv = sD[(0 * 2 + buf) * 32 + (dlbase | 3)];
                GP_MASK(3, dv, smC[3], wv.x, wv.y, wv.z, wv.w, pB0, pB1, pB2, pB3);
            }
            float n0 = pA0 + pB0, n1 = pA1 + pB1, n2 = pA2 + pB2, n3 = pA3 + pB3;

            // scale-only normalize
            float ss = n0 * n0 + n1 * n1;
            ss = fmaf(n2, n2, ss);
            ss = fmaf(n3, n3, ss);
            ss += __shfl_xor_sync(FULLMASK, ss, 1);
            ss += __shfl_xor_sync(FULLMASK, ss, 2);
            ss += __shfl_xor_sync(FULLMASK, ss, 4);
            const float r = rsqrtf(ss + 1e-30f);
            c0 = n0 * r; c1 = n1 * r; c2 = n2 * r; c3 = n3 * r;
        }
    }
    __syncthreads();

    // =========================== Phase C ===================================
    // psi_t = P_{seg,i} * C_seg ; exact normalize ; fused projection.
    {
        // transformed output weights
        float wo[4][Dd];
#pragma unroll
        for (int r = 0; r < 4; ++r) {
            const unsigned E  = lift4((unsigned)(g2 * 4 + r));
            const unsigned Ed = E ^ 31u;
            const float sOut = csn(31u, E) ? -1.0f : 1.0f;
            const float coef = half ? -sOut : sOut;
            const int colE = h * 32 + (int)E, colD = h * 32 + (int)Ed;
#pragma unroll
            for (int d = 0; d < Dd; ++d)
                wo[r][d] = __ldg(W_out + colE * Dd + d) + coef * __ldg(W_out + colD * Dd + d);
        }

        float4 Creg[4];
#pragma unroll
        for (int m = 0; m < 4; ++m) Creg[m] = sC[seg * 32 + (lane ^ m)];

        float* pw = g_part + ((size_t)(c * Ss + seg * SEGL)) * 24 + hq * 6 + lane;

#pragma unroll 1
        for (int i = 0; i < SEGL; ++i) {
            const int row = seg * SEGL + i;
            float pA0 = 0.f, pA1 = 0.f, pA2 = 0.f, pA3 = 0.f;
            float pB0 = 0.f, pB1 = 0.f, pB2 = 0.f, pB3 = 0.f;
            {   const float4 dv = sP[row * 32 + dlbase];
                GP_MASK(0, dv, smC[0], Creg[0].x, Creg[0].y, Creg[0].z, Creg[0].w,
                        pA0, pA1, pA2, pA3);
            }
            {   const float4 dv = sP[row * 32 + (dlbase | 1)];
                GP_MASK(1, dv, smC[1], Creg[1].x, Creg[1].y, Creg[1].z, Creg[1].w,
                        pB0, pB1, pB2, pB3);
            }
            {   const float4 dv = sP[row * 32 + (dlbase | 2)];
                GP_MASK(2, dv, smC[2], Creg[2].x, Creg[2].y, Creg[2].z, Creg[2].w,
                        pA0, pA1, pA2, pA3);
            }
            {   const float4 dv = sP[row * 32 + (dlbase | 3)];
                GP_MASK(3, dv, smC[3], Creg[3].x, Creg[3].y, Creg[3].z, Creg[3].w,
                        pB0, pB1, pB2, pB3);
            }
            const float nw0 = pA0 + pB0, nw1 = pA1 + pB1;
            const float nw2 = pA2 + pB2, nw3 = pA3 + pB3;

            // exact normalize: |psi|^2 = 2*(per-head 8-lane sum), + NR step
            float s = nw0 * nw0 + nw1 * nw1;
            s = fmaf(nw2, nw2, s);
            s = fmaf(nw3, nw3, s);
            s += __shfl_xor_sync(FULLMASK, s, 1);
            s += __shfl_xor_sync(FULLMASK, s, 2);
            s += __shfl_xor_sync(FULLMASK, s, 4);
            s = s + s + 1e-30f;
            float rn = rsqrtf(s);
            rn = rn * (1.5f - 0.5f * s * rn * rn);
            const float st0 = nw0 * rn, st1 = nw1 * rn;
            const float st2 = nw2 * rn, st3 = nw3 * rn;

            // projection partials
            float p0, p1, p2, p3, p4, p5;
            p0 = st0 * wo[0][0]; p1 = st0 * wo[0][1]; p2 = st0 * wo[0][2];
            p3 = st0 * wo[0][3]; p4 = st0 * wo[0][4]; p5 = st0 * wo[0][5];
            p0 = fmaf(st1, wo[1][0], p0); p1 = fmaf(st1, wo[1][1], p1);
            p2 = fmaf(st1, wo[1][2], p2); p3 = fmaf(st1, wo[1][3], p3);
            p4 = fmaf(st1, wo[1][4], p4); p5 = fmaf(st1, wo[1][5], p5);
            p0 = fmaf(st2, wo[2][0], p0); p1 = fmaf(st2, wo[2][1], p1);
            p2 = fmaf(st2, wo[2][2], p2); p3 = fmaf(st2, wo[2][3], p3);
            p4 = fmaf(st2, wo[2][4], p4); p5 = fmaf(st2, wo[2][5], p5);
            p0 = fmaf(st3, wo[3][0], p0); p1 = fmaf(st3, wo[3][1], p1);
            p2 = fmaf(st3, wo[3][2], p2); p3 = fmaf(st3, wo[3][3], p3);
            p4 = fmaf(st3, wo[3][4], p4); p5 = fmaf(st3, wo[3][5], p5);
            // full 32-lane reduce: sums both halves AND the quad's 4 heads
#pragma unroll
            for (int o = 1; o < 32; o <<= 1) {
                p0 += __shfl_xor_sync(FULLMASK, p0, o);
                p1 += __shfl_xor_sync(FULLMASK, p1, o);
                p2 += __shfl_xor_sync(FULLMASK, p2, o);
                p3 += __shfl_xor_sync(FULLMASK, p3, o);
                p4 += __shfl_xor_sync(FULLMASK, p4, o);
                p5 += __shfl_xor_sync(FULLMASK, p5, o);
            }
            const float pv = (lane == 0) ? p0 : (lane == 1) ? p1 : (lane == 2) ? p2
                           : (lane == 3) ? p3 : (lane == 4) ? p4 : p5;
            if (lane < 6) *pw = pv;
            pw += 24;
        }
    }
}

// ---------------------------------------------------------------------------
// Combine: y[row,d] = x[row,d] + b_out[d] + sum_{4 hq} g_part[row][hq][d]
// ---------------------------------------------------------------------------
__global__ void __launch_bounds__(256) combine_kernel(
    const float* __restrict__ x,
    const float* __restrict__ b_out,
    float* __restrict__ y)
{
    const int e   = blockIdx.x * blockDim.x + threadIdx.x;  // 0..393215
    const int row = e / 6;              // chain*256 + t
    const int d   = e - row * 6;

    const float* pp = g_part + (size_t)row * 24 + d;
    float acc = __ldg(b_out + d)
              + (__ldg(pp) + __ldg(pp + 6)) + (__ldg(pp + 12) + __ldg(pp + 18));

    const int c = row >> 8;
    const int t = row & (Ss - 1);
    const int b = c >> 4;
    const int n = c & (Nn - 1);
    const size_t off = (((size_t)b * Ss + t) * Nn + n) * Dd + d;
    y[off] = __ldg(x + off) + acc;
}

extern "C" void kernel_launch(void* const* d_in, const int* in_sizes, int n_in,
                              void* d_out, int out_size) {
    const float* x     = (const float*)d_in[0];
    const float* W_in  = (const float*)d_in[1];
    const float* b_in  = (const float*)d_in[2];
    const float* W_out = (const float*)d_in[3];
    const float* b_out = (const float*)d_in[4];
    float* y = (float*)d_out;

    static int attr_set = 0;
    if (!attr_set) {
        cudaFuncSetAttribute(fused_kernel,
                             cudaFuncAttributeMaxDynamicSharedMemorySize, SMEM_BYTES);
        attr_set = 1;
    }

    // Fused scan: 1024 blocks = 256 chains x 4 head-quads, 512 threads each
    fused_kernel<<<1024, 512, SMEM_BYTES>>>(x, W_in, b_in, W_out);
    // Combine
    combine_kernel<<<1536, 256>>>(x, b_out, y);
}